// round 1
// baseline (speedup 1.0000x reference)
#include <cuda_runtime.h>
#include <cuda_bf16.h>
#include <cstdint>

// Problem constants
#define Bq   4
#define Nq   8192
#define DIMq 512
#define HEADSq 8
#define DHq  64
#define INNERq 512
#define QKV_COLS 1536
#define M_TOTAL (Bq * Nq)          // 32768
#define BH (Bq * HEADSq)           // 32
#define SCALEq 0.125f              // 64^-0.5

// ---------------- scratch (device globals; no allocation allowed) ----------
__device__ float g_qkv[M_TOTAL * QKV_COLS];    // 201 MB
__device__ float g_R[M_TOTAL * INNERq];        // 67 MB
__device__ float g_logits[BH * Nq];            // 1 MB
__device__ float g_gq[BH * DHq];
__device__ float g_gk[BH * DHq];
__device__ float g_wvec[BH * DHq];

// ---------------- generic TN SGEMM: C[M,N] = A[M,K] @ B[N,K]^T (+bias) -----
// BM=128, BN=128, BK=16, 256 threads, 8x8 thread tile.
template <bool BIAS>
__global__ __launch_bounds__(256)
void sgemm_tn(const float* __restrict__ A, const float* __restrict__ B,
              const float* __restrict__ bias, float* __restrict__ C,
              int M, int N, int K) {
    constexpr int BM = 128, BN = 128, BK = 16;
    __shared__ float As[BK][BM + 4];
    __shared__ float Bs[BK][BN + 4];

    const int tid = threadIdx.x;
    const int bm = blockIdx.y * BM;
    const int bn = blockIdx.x * BN;
    const int tx = tid & 15;       // 16 threads along N
    const int ty = tid >> 4;       // 16 threads along M

    const int lrow  = tid >> 2;    // 0..63
    const int lcol4 = tid & 3;     // which float4 along K (BK=16 -> 4)

    float acc[8][8];
#pragma unroll
    for (int i = 0; i < 8; i++)
#pragma unroll
        for (int j = 0; j < 8; j++) acc[i][j] = 0.f;

    for (int k0 = 0; k0 < K; k0 += BK) {
#pragma unroll
        for (int it = 0; it < 2; it++) {
            int r = lrow + it * 64;
            float4 va = *reinterpret_cast<const float4*>(
                A + (size_t)(bm + r) * K + k0 + lcol4 * 4);
            As[lcol4 * 4 + 0][r] = va.x;
            As[lcol4 * 4 + 1][r] = va.y;
            As[lcol4 * 4 + 2][r] = va.z;
            As[lcol4 * 4 + 3][r] = va.w;
            float4 vb = *reinterpret_cast<const float4*>(
                B + (size_t)(bn + r) * K + k0 + lcol4 * 4);
            Bs[lcol4 * 4 + 0][r] = vb.x;
            Bs[lcol4 * 4 + 1][r] = vb.y;
            Bs[lcol4 * 4 + 2][r] = vb.z;
            Bs[lcol4 * 4 + 3][r] = vb.w;
        }
        __syncthreads();

#pragma unroll
        for (int kk = 0; kk < BK; kk++) {
            float ar[8], br[8];
#pragma unroll
            for (int i = 0; i < 8; i++) ar[i] = As[kk][ty * 8 + i];
#pragma unroll
            for (int j = 0; j < 8; j++) br[j] = Bs[kk][tx * 8 + j];
#pragma unroll
            for (int i = 0; i < 8; i++)
#pragma unroll
                for (int j = 0; j < 8; j++) acc[i][j] += ar[i] * br[j];
        }
        __syncthreads();
    }

#pragma unroll
    for (int i = 0; i < 8; i++) {
        int row = bm + ty * 8 + i;
#pragma unroll
        for (int j = 0; j < 8; j++) {
            int col = bn + tx * 8 + j;
            float v = acc[i][j];
            if (BIAS) v += bias[col];
            C[(size_t)row * N + col] = v;
        }
    }
}

// ---------------- per-(b,h) logit weight vectors --------------------------
__global__ void make_wq(const float* __restrict__ wql, float* __restrict__ wvec) {
    int t = blockIdx.x * blockDim.x + threadIdx.x;
    if (t < BH * DHq) wvec[t] = wql[t & 63];
}
__global__ void make_wk(const float* __restrict__ wkl, const float* __restrict__ gq,
                        float* __restrict__ wvec) {
    int t = blockIdx.x * blockDim.x + threadIdx.x;
    if (t < BH * DHq) wvec[t] = wkl[t & 63] * gq[t];
}

// ---------------- logits: one warp per (bh, n') token ----------------------
// Token mapping from the reference's reshape: for head h, token n' lives at
// row = h*1024 + (n'>>3), colblock = n'&7 of the [8192, 512] per-batch slab.
__global__ __launch_bounds__(256)
void logits_kernel(const float* __restrict__ qkv, int off,
                   const float* __restrict__ wvec,
                   const unsigned char* __restrict__ mask,
                   float* __restrict__ logits) {
    int gw = (blockIdx.x * blockDim.x + threadIdx.x) >> 5;
    int lane = threadIdx.x & 31;
    int np = gw & (Nq - 1);
    int bh = gw >> 13;
    int b = bh >> 3, h = bh & 7;
    int row = h * 1024 + (np >> 3);
    int j0 = (np & 7) * 64;
    const float* p = qkv + (size_t)(b * Nq + row) * QKV_COLS + off + j0;
    const float* w = wvec + bh * 64;
    float s = p[lane] * w[lane] + p[lane + 32] * w[lane + 32];
#pragma unroll
    for (int o = 16; o > 0; o >>= 1) s += __shfl_xor_sync(0xffffffffu, s, o);
    if (lane == 0) {
        float v = s * SCALEq;
        if (mask[b * Nq + np]) v = -1e30f;
        logits[bh * Nq + np] = v;
    }
}

// ---------------- softmax + weighted 64-vec reduction per (b,h) -----------
__global__ __launch_bounds__(256)
void softmax_reduce(const float* __restrict__ logits,
                    const float* __restrict__ qkv, int off,
                    float* __restrict__ gout) {
    int bh = blockIdx.x;
    int b = bh >> 3, h = bh & 7;
    const float* lrow = logits + bh * Nq;
    __shared__ float red[256];
    int t = threadIdx.x;

    // pass 1: max
    float m = -1e30f;
    for (int n = t; n < Nq; n += 256) m = fmaxf(m, lrow[n]);
    red[t] = m;
    __syncthreads();
    for (int s = 128; s > 0; s >>= 1) {
        if (t < s) red[t] = fmaxf(red[t], red[t + s]);
        __syncthreads();
    }
    float M = red[0];
    __syncthreads();

    // pass 2: weighted sum
    int d = t & 63, g = t >> 6;
    float vacc = 0.f, sacc = 0.f;
    for (int np = g; np < Nq; np += 4) {
        int row = h * 1024 + (np >> 3);
        int j0 = (np & 7) * 64;
        float wgt = __expf(lrow[np] - M);
        sacc += wgt;
        vacc += wgt * qkv[(size_t)(b * Nq + row) * QKV_COLS + off + j0 + d];
    }
    __shared__ float sv[4][64];
    __shared__ float ss[4];
    sv[g][d] = vacc;
    if (d == 0) ss[g] = sacc;
    __syncthreads();
    if (t < 64) {
        float v = sv[0][t] + sv[1][t] + sv[2][t] + sv[3][t];
        float S = ss[0] + ss[1] + ss[2] + ss[3];
        gout[bh * 64 + t] = v / S;
    }
}

// ---------------- r = (v * gk) @ W_r^T + b_r + q ---------------------------
// Per global row m: head h = (m % 8192) / 1024 (all 8 colblocks share h).
__global__ __launch_bounds__(256)
void compute_r_kernel(const float* __restrict__ qkv,
                      const float* __restrict__ gk,
                      const float* __restrict__ W_r,
                      const float* __restrict__ b_r,
                      float* __restrict__ R) {
    constexpr int ROWS = 8;
    int t = threadIdx.x;
    int e = t & 63;
    int cb1 = t >> 6;            // colblocks 0..3 (also does cb1+4)
    int row0 = blockIdx.x * ROWS;
    int b = row0 >> 13;
    int h = (row0 & (Nq - 1)) >> 10;

    __shared__ float vg[512];
    __shared__ float gkh[64];

    // W_r row e in registers (reused across all rows)
    float w[64];
#pragma unroll
    for (int d0 = 0; d0 < 64; d0 += 4) {
        float4 v4 = *reinterpret_cast<const float4*>(W_r + e * 64 + d0);
        w[d0] = v4.x; w[d0 + 1] = v4.y; w[d0 + 2] = v4.z; w[d0 + 3] = v4.w;
    }
    float br = b_r[e];
    if (t < 64) gkh[t] = gk[(b * 8 + h) * 64 + t];
    __syncthreads();

    for (int r = 0; r < ROWS; r++) {
        int m = row0 + r;
        const float* vrow = qkv + (size_t)m * QKV_COLS + 1024;
        vg[t]       = vrow[t]       * gkh[t & 63];
        vg[t + 256] = vrow[t + 256] * gkh[t & 63];
        __syncthreads();

        float a1 = br, a2 = br;
#pragma unroll
        for (int d = 0; d < 64; d += 4) {
            float4 v1 = *reinterpret_cast<const float4*>(&vg[cb1 * 64 + d]);
            float4 v2 = *reinterpret_cast<const float4*>(&vg[(cb1 + 4) * 64 + d]);
            a1 += v1.x * w[d] + v1.y * w[d + 1] + v1.z * w[d + 2] + v1.w * w[d + 3];
            a2 += v2.x * w[d] + v2.y * w[d + 1] + v2.z * w[d + 2] + v2.w * w[d + 3];
        }
        const float* qrow = qkv + (size_t)m * QKV_COLS;
        R[(size_t)m * INNERq + cb1 * 64 + e]       = a1 + qrow[cb1 * 64 + e];
        R[(size_t)m * INNERq + (cb1 + 4) * 64 + e] = a2 + qrow[(cb1 + 4) * 64 + e];
        __syncthreads();
    }
}

// ---------------- launcher --------------------------------------------------
extern "C" void kernel_launch(void* const* d_in, const int* in_sizes, int n_in,
                              void* d_out, int out_size) {
    const float* x     = (const float*)d_in[0];
    const unsigned char* mask = (const unsigned char*)d_in[1];
    const float* W_qkv = (const float*)d_in[2];
    const float* w_q   = (const float*)d_in[3];
    const float* w_k   = (const float*)d_in[4];
    const float* W_r   = (const float*)d_in[5];
    const float* b_r   = (const float*)d_in[6];
    const float* W_out = (const float*)d_in[7];
    const float* b_out = (const float*)d_in[8];
    float* out = (float*)d_out;

    float *qkv, *R, *logits, *gq, *gk, *wvec;
    cudaGetSymbolAddress((void**)&qkv,    g_qkv);
    cudaGetSymbolAddress((void**)&R,      g_R);
    cudaGetSymbolAddress((void**)&logits, g_logits);
    cudaGetSymbolAddress((void**)&gq,     g_gq);
    cudaGetSymbolAddress((void**)&gk,     g_gk);
    cudaGetSymbolAddress((void**)&wvec,   g_wvec);

    // 1) qkv = x @ W_qkv^T   (M=32768, N=1536, K=512)
    sgemm_tn<false><<<dim3(QKV_COLS / 128, M_TOTAL / 128), 256>>>(
        x, W_qkv, nullptr, qkv, M_TOTAL, QKV_COLS, DIMq);

    // 2) q softmax -> global_q
    make_wq<<<(BH * DHq + 255) / 256, 256>>>(w_q, wvec);
    logits_kernel<<<BH * Nq / 8, 256>>>(qkv, 0, wvec, mask, logits);
    softmax_reduce<<<BH, 256>>>(logits, qkv, 0, gq);

    // 3) k softmax (weight = gq * w_k) -> global_k
    make_wk<<<(BH * DHq + 255) / 256, 256>>>(w_k, gq, wvec);
    logits_kernel<<<BH * Nq / 8, 256>>>(qkv, DIMq, wvec, mask, logits);
    softmax_reduce<<<BH, 256>>>(logits, qkv, DIMq, gk);

    // 4) r = (v*gk) @ W_r^T + b_r + q
    compute_r_kernel<<<M_TOTAL / 8, 256>>>(qkv, gk, W_r, b_r, R);

    // 5) out = r @ W_out^T + b_out  (M=32768, N=512, K=512)
    sgemm_tn<true><<<dim3(INNERq / 128, M_TOTAL / 128), 256>>>(
        R, W_out, b_out, out, M_TOTAL, INNERq, DIMq);
}

// round 2
// speedup vs baseline: 1.2700x; 1.2700x over previous
#include <cuda_runtime.h>
#include <cuda_bf16.h>
#include <cstdint>

// Problem constants
#define Bq   4
#define Nq   8192
#define DIMq 512
#define HEADSq 8
#define DHq  64
#define INNERq 512
#define QKV_COLS 1536
#define M_TOTAL (Bq * Nq)          // 32768
#define BH (Bq * HEADSq)           // 32
#define SCALEq 0.125f              // 64^-0.5
#define CHUNKS 32                  // softmax reduce chunks per (b,h)
#define REC 65                     // partial record: 64 sums + 1 weight

// ---------------- scratch (device globals; no allocation allowed) ----------
__device__ float g_qkv[M_TOTAL * QKV_COLS];    // 201 MB
__device__ float g_R[M_TOTAL * INNERq];        // 67 MB
__device__ float g_logits[BH * Nq];            // 1 MB
__device__ float g_gq[BH * DHq];
__device__ float g_gk[BH * DHq];
__device__ float g_wvec[BH * DHq];
__device__ float g_part[BH * CHUNKS * REC];
__device__ float g_max[BH];

// ---------------- generic TN SGEMM: C[M,N] = A[M,K] @ B[N,K]^T (+bias) -----
template <bool BIAS>
__global__ __launch_bounds__(256)
void sgemm_tn(const float* __restrict__ A, const float* __restrict__ B,
              const float* __restrict__ bias, float* __restrict__ C,
              int M, int N, int K) {
    constexpr int BM = 128, BN = 128, BK = 16;
    __shared__ float As[BK][BM + 4];
    __shared__ float Bs[BK][BN + 4];

    const int tid = threadIdx.x;
    const int bm = blockIdx.y * BM;
    const int bn = blockIdx.x * BN;
    const int tx = tid & 15;
    const int ty = tid >> 4;

    const int lrow  = tid >> 2;
    const int lcol4 = tid & 3;

    float acc[8][8];
#pragma unroll
    for (int i = 0; i < 8; i++)
#pragma unroll
        for (int j = 0; j < 8; j++) acc[i][j] = 0.f;

    for (int k0 = 0; k0 < K; k0 += BK) {
#pragma unroll
        for (int it = 0; it < 2; it++) {
            int r = lrow + it * 64;
            float4 va = *reinterpret_cast<const float4*>(
                A + (size_t)(bm + r) * K + k0 + lcol4 * 4);
            As[lcol4 * 4 + 0][r] = va.x;
            As[lcol4 * 4 + 1][r] = va.y;
            As[lcol4 * 4 + 2][r] = va.z;
            As[lcol4 * 4 + 3][r] = va.w;
            float4 vb = *reinterpret_cast<const float4*>(
                B + (size_t)(bn + r) * K + k0 + lcol4 * 4);
            Bs[lcol4 * 4 + 0][r] = vb.x;
            Bs[lcol4 * 4 + 1][r] = vb.y;
            Bs[lcol4 * 4 + 2][r] = vb.z;
            Bs[lcol4 * 4 + 3][r] = vb.w;
        }
        __syncthreads();

#pragma unroll
        for (int kk = 0; kk < BK; kk++) {
            float ar[8], br[8];
#pragma unroll
            for (int i = 0; i < 8; i++) ar[i] = As[kk][ty * 8 + i];
#pragma unroll
            for (int j = 0; j < 8; j++) br[j] = Bs[kk][tx * 8 + j];
#pragma unroll
            for (int i = 0; i < 8; i++)
#pragma unroll
                for (int j = 0; j < 8; j++) acc[i][j] += ar[i] * br[j];
        }
        __syncthreads();
    }

#pragma unroll
    for (int i = 0; i < 8; i++) {
        int row = bm + ty * 8 + i;
#pragma unroll
        for (int j = 0; j < 8; j++) {
            int col = bn + tx * 8 + j;
            float v = acc[i][j];
            if (BIAS) v += bias[col];
            C[(size_t)row * N + col] = v;
        }
    }
}

// ---------------- per-(b,h) logit weight vectors --------------------------
__global__ void make_wq(const float* __restrict__ wql, float* __restrict__ wvec) {
    int t = blockIdx.x * blockDim.x + threadIdx.x;
    if (t < BH * DHq) wvec[t] = wql[t & 63];
}
__global__ void make_wk(const float* __restrict__ wkl, const float* __restrict__ gq,
                        float* __restrict__ wvec) {
    int t = blockIdx.x * blockDim.x + threadIdx.x;
    if (t < BH * DHq) wvec[t] = wkl[t & 63] * gq[t];
}

// ---------------- logits: one warp per (bh, n') token ----------------------
// Token mapping from the reference's reshape: for head h, token n' lives at
// row = h*1024 + (n'>>3), colblock = n'&7 of the [8192, 512] per-batch slab.
__global__ __launch_bounds__(256)
void logits_kernel(const float* __restrict__ qkv, int off,
                   const float* __restrict__ wvec,
                   const unsigned char* __restrict__ mask,
                   float* __restrict__ logits) {
    int gw = (blockIdx.x * blockDim.x + threadIdx.x) >> 5;
    int lane = threadIdx.x & 31;
    int np = gw & (Nq - 1);
    int bh = gw >> 13;
    int b = bh >> 3, h = bh & 7;
    int row = h * 1024 + (np >> 3);
    int j0 = (np & 7) * 64;
    const float* p = qkv + (size_t)(b * Nq + row) * QKV_COLS + off + j0;
    const float* w = wvec + bh * 64;
    float s = p[lane] * w[lane] + p[lane + 32] * w[lane + 32];
#pragma unroll
    for (int o = 16; o > 0; o >>= 1) s += __shfl_xor_sync(0xffffffffu, s, o);
    if (lane == 0) {
        float v = s * SCALEq;
        if (mask[b * Nq + np]) v = -1e30f;
        logits[bh * Nq + np] = v;
    }
}

// ---------------- per-(b,h) max over 8192 logits ---------------------------
__global__ __launch_bounds__(256)
void max_kernel(const float* __restrict__ logits, float* __restrict__ gmax) {
    int bh = blockIdx.x;
    const float* lrow = logits + bh * Nq;
    int t = threadIdx.x;
    float m = -1e30f;
    for (int n = t; n < Nq; n += 256) m = fmaxf(m, lrow[n]);
    __shared__ float red[256];
    red[t] = m;
    __syncthreads();
    for (int s = 128; s > 0; s >>= 1) {
        if (t < s) red[t] = fmaxf(red[t], red[t + s]);
        __syncthreads();
    }
    if (t == 0) gmax[bh] = red[0];
}

// ---------------- partial exp-weighted reduction ---------------------------
// grid = (CHUNKS, BH). Each block: 256 tokens of one (b,h); writes a
// deterministic partial record: 64 weighted sums + sum of weights.
__global__ __launch_bounds__(256)
void partial_reduce(const float* __restrict__ logits,
                    const float* __restrict__ qkv, int off,
                    const float* __restrict__ gmax,
                    float* __restrict__ part) {
    int c = blockIdx.x;
    int bh = blockIdx.y;
    int b = bh >> 3, h = bh & 7;
    const float* lrow = logits + bh * Nq;
    float M = gmax[bh];

    int t = threadIdx.x;
    int d = t & 63, g = t >> 6;      // 4 groups of 64 threads
    int n0 = c * 256;

    float vacc = 0.f, sacc = 0.f;
    for (int np = n0 + g; np < n0 + 256; np += 4) {
        int row = h * 1024 + (np >> 3);
        int j0 = (np & 7) * 64;
        float wgt = __expf(lrow[np] - M);
        sacc += wgt;
        vacc += wgt * qkv[(size_t)(b * Nq + row) * QKV_COLS + off + j0 + d];
    }

    __shared__ float sv[4][64];
    __shared__ float ss[4];
    sv[g][d] = vacc;
    if (d == 0) ss[g] = sacc;
    __syncthreads();
    if (t < 64) {
        float* rec = part + (size_t)(bh * CHUNKS + c) * REC;
        rec[t] = sv[0][t] + sv[1][t] + sv[2][t] + sv[3][t];
        if (t == 0) rec[64] = ss[0] + ss[1] + ss[2] + ss[3];
    }
}

// ---------------- finalize: sum partials, divide by total weight ----------
__global__ void finalize_reduce(const float* __restrict__ part,
                                float* __restrict__ gout) {
    int bh = blockIdx.x;
    int d = threadIdx.x;    // 64 threads
    const float* base = part + (size_t)bh * CHUNKS * REC;
    float v = 0.f, w = 0.f;
#pragma unroll
    for (int c = 0; c < CHUNKS; c++) {
        v += base[c * REC + d];
        w += base[c * REC + 64];
    }
    gout[bh * 64 + d] = v / w;
}

// ---------------- r = (v * gk) @ W_r^T + b_r + q ---------------------------
__global__ __launch_bounds__(256)
void compute_r_kernel(const float* __restrict__ qkv,
                      const float* __restrict__ gk,
                      const float* __restrict__ W_r,
                      const float* __restrict__ b_r,
                      float* __restrict__ R) {
    constexpr int ROWS = 8;
    int t = threadIdx.x;
    int e = t & 63;
    int cb1 = t >> 6;
    int row0 = blockIdx.x * ROWS;
    int b = row0 >> 13;
    int h = (row0 & (Nq - 1)) >> 10;

    __shared__ float vg[512];
    __shared__ float gkh[64];

    float w[64];
#pragma unroll
    for (int d0 = 0; d0 < 64; d0 += 4) {
        float4 v4 = *reinterpret_cast<const float4*>(W_r + e * 64 + d0);
        w[d0] = v4.x; w[d0 + 1] = v4.y; w[d0 + 2] = v4.z; w[d0 + 3] = v4.w;
    }
    float br = b_r[e];
    if (t < 64) gkh[t] = gk[(b * 8 + h) * 64 + t];
    __syncthreads();

    for (int r = 0; r < ROWS; r++) {
        int m = row0 + r;
        const float* vrow = qkv + (size_t)m * QKV_COLS + 1024;
        vg[t]       = vrow[t]       * gkh[t & 63];
        vg[t + 256] = vrow[t + 256] * gkh[t & 63];
        __syncthreads();

        float a1 = br, a2 = br;
#pragma unroll
        for (int d = 0; d < 64; d += 4) {
            float4 v1 = *reinterpret_cast<const float4*>(&vg[cb1 * 64 + d]);
            float4 v2 = *reinterpret_cast<const float4*>(&vg[(cb1 + 4) * 64 + d]);
            a1 += v1.x * w[d] + v1.y * w[d + 1] + v1.z * w[d + 2] + v1.w * w[d + 3];
            a2 += v2.x * w[d] + v2.y * w[d + 1] + v2.z * w[d + 2] + v2.w * w[d + 3];
        }
        const float* qrow = qkv + (size_t)m * QKV_COLS;
        R[(size_t)m * INNERq + cb1 * 64 + e]       = a1 + qrow[cb1 * 64 + e];
        R[(size_t)m * INNERq + (cb1 + 4) * 64 + e] = a2 + qrow[(cb1 + 4) * 64 + e];
        __syncthreads();
    }
}

// ---------------- launcher --------------------------------------------------
extern "C" void kernel_launch(void* const* d_in, const int* in_sizes, int n_in,
                              void* d_out, int out_size) {
    const float* x     = (const float*)d_in[0];
    const unsigned char* mask = (const unsigned char*)d_in[1];
    const float* W_qkv = (const float*)d_in[2];
    const float* w_q   = (const float*)d_in[3];
    const float* w_k   = (const float*)d_in[4];
    const float* W_r   = (const float*)d_in[5];
    const float* b_r   = (const float*)d_in[6];
    const float* W_out = (const float*)d_in[7];
    const float* b_out = (const float*)d_in[8];
    float* out = (float*)d_out;

    float *qkv, *R, *logits, *gq, *gk, *wvec, *part, *gmax;
    cudaGetSymbolAddress((void**)&qkv,    g_qkv);
    cudaGetSymbolAddress((void**)&R,      g_R);
    cudaGetSymbolAddress((void**)&logits, g_logits);
    cudaGetSymbolAddress((void**)&gq,     g_gq);
    cudaGetSymbolAddress((void**)&gk,     g_gk);
    cudaGetSymbolAddress((void**)&wvec,   g_wvec);
    cudaGetSymbolAddress((void**)&part,   g_part);
    cudaGetSymbolAddress((void**)&gmax,   g_max);

    // 1) qkv = x @ W_qkv^T   (M=32768, N=1536, K=512)
    sgemm_tn<false><<<dim3(QKV_COLS / 128, M_TOTAL / 128), 256>>>(
        x, W_qkv, nullptr, qkv, M_TOTAL, QKV_COLS, DIMq);

    // 2) q softmax -> global_q
    make_wq<<<(BH * DHq + 255) / 256, 256>>>(w_q, wvec);
    logits_kernel<<<BH * Nq / 8, 256>>>(qkv, 0, wvec, mask, logits);
    max_kernel<<<BH, 256>>>(logits, gmax);
    partial_reduce<<<dim3(CHUNKS, BH), 256>>>(logits, qkv, 0, gmax, part);
    finalize_reduce<<<BH, 64>>>(part, gq);

    // 3) k softmax (weight = gq * w_k) -> global_k
    make_wk<<<(BH * DHq + 255) / 256, 256>>>(w_k, gq, wvec);
    logits_kernel<<<BH * Nq / 8, 256>>>(qkv, DIMq, wvec, mask, logits);
    max_kernel<<<BH, 256>>>(logits, gmax);
    partial_reduce<<<dim3(CHUNKS, BH), 256>>>(logits, qkv, DIMq, gmax, part);
    finalize_reduce<<<BH, 64>>>(part, gk);

    // 4) r = (v*gk) @ W_r^T + b_r + q
    compute_r_kernel<<<M_TOTAL / 8, 256>>>(qkv, gk, W_r, b_r, R);

    // 5) out = r @ W_out^T + b_out  (M=32768, N=512, K=512)
    sgemm_tn<true><<<dim3(INNERq / 128, M_TOTAL / 128), 256>>>(
        R, W_out, b_out, out, M_TOTAL, INNERq, DIMq);
}

// round 4
// speedup vs baseline: 2.4154x; 1.9019x over previous
#include <cuda_runtime.h>
#include <cuda_bf16.h>
#include <cstdint>

// Problem constants
#define Bq   4
#define Nq   8192
#define DIMq 512
#define HEADSq 8
#define DHq  64
#define INNERq 512
#define QKV_COLS 1536
#define M_TOTAL (Bq * Nq)          // 32768
#define BH (Bq * HEADSq)           // 32
#define SCALEq 0.125f
#define CHUNKS 32
#define REC 65

// ---------------- scratch (device globals; no allocation allowed) ----------
__device__ __align__(128) float g_qkv[M_TOTAL * QKV_COLS];      // 201 MB fp32
__device__ __align__(128) __nv_bfloat16 g_xh[M_TOTAL * DIMq];
__device__ __align__(128) __nv_bfloat16 g_xl[M_TOTAL * DIMq];
__device__ __align__(128) __nv_bfloat16 g_Rh[M_TOTAL * INNERq];
__device__ __align__(128) __nv_bfloat16 g_Rl[M_TOTAL * INNERq];
__device__ __align__(128) __nv_bfloat16 g_Wqh[QKV_COLS * DIMq];
__device__ __align__(128) __nv_bfloat16 g_Wql[QKV_COLS * DIMq];
__device__ __align__(128) __nv_bfloat16 g_Woh[DIMq * INNERq];
__device__ __align__(128) __nv_bfloat16 g_Wol[DIMq * INNERq];
__device__ float g_logits[BH * Nq];
__device__ float g_gq[BH * DHq];
__device__ float g_gk[BH * DHq];
__device__ float g_wvec[BH * DHq];
__device__ float g_part[BH * CHUNKS * REC];
__device__ float g_max[BH];

// =================== base-ISA helpers (sm_80+: cp.async / ldmatrix / mma) ===
__device__ __forceinline__ uint32_t smem_u32(const void* p) {
    uint32_t a;
    asm("{ .reg .u64 t; cvta.to.shared.u64 t, %1; cvt.u32.u64 %0, t; }"
        : "=r"(a) : "l"(p));
    return a;
}
__device__ __forceinline__ void cp_async16(uint32_t dst, const void* src) {
    asm volatile("cp.async.cg.shared.global [%0], [%1], 16;"
                 :: "r"(dst), "l"(src));
}
__device__ __forceinline__ void cp_commit() {
    asm volatile("cp.async.commit_group;");
}
template <int N>
__device__ __forceinline__ void cp_wait() {
    asm volatile("cp.async.wait_group %0;" :: "n"(N));
}
__device__ __forceinline__ void ldsm_x4(uint32_t addr, uint32_t& r0, uint32_t& r1,
                                        uint32_t& r2, uint32_t& r3) {
    asm volatile("ldmatrix.sync.aligned.m8n8.x4.shared.b16 {%0,%1,%2,%3}, [%4];"
                 : "=r"(r0), "=r"(r1), "=r"(r2), "=r"(r3) : "r"(addr));
}
__device__ __forceinline__ void mma_16816(float* c, const uint32_t* a,
                                          uint32_t b0, uint32_t b1) {
    asm volatile(
        "mma.sync.aligned.m16n8k16.row.col.f32.bf16.bf16.f32 "
        "{%0,%1,%2,%3}, {%4,%5,%6,%7}, {%8,%9}, {%0,%1,%2,%3};"
        : "+f"(c[0]), "+f"(c[1]), "+f"(c[2]), "+f"(c[3])
        : "r"(a[0]), "r"(a[1]), "r"(a[2]), "r"(a[3]), "r"(b0), "r"(b1));
}

// =================== hi/lo split conversion =================================
__device__ __forceinline__ void split2(float a, float b, uint32_t& hi2, uint32_t& lo2) {
    __nv_bfloat162 h = __float22bfloat162_rn(make_float2(a, b));
    float ra = a - __bfloat162float(h.x);
    float rb = b - __bfloat162float(h.y);
    __nv_bfloat162 l = __float22bfloat162_rn(make_float2(ra, rb));
    hi2 = *reinterpret_cast<uint32_t*>(&h);
    lo2 = *reinterpret_cast<uint32_t*>(&l);
}

__global__ __launch_bounds__(256)
void split_kernel(const float* __restrict__ in, __nv_bfloat16* __restrict__ hi,
                  __nv_bfloat16* __restrict__ lo) {
    size_t i = ((size_t)blockIdx.x * 256 + threadIdx.x) * 4;
    float4 v = *reinterpret_cast<const float4*>(in + i);
    uint32_t h0, l0, h1, l1;
    split2(v.x, v.y, h0, l0);
    split2(v.z, v.w, h1, l1);
    *reinterpret_cast<uint2*>(hi + i) = make_uint2(h0, h1);
    *reinterpret_cast<uint2*>(lo + i) = make_uint2(l0, l1);
}

// =================== HMMA split-bf16 GEMM (base ISA) ========================
// C[M,Ntot] = A[M,512] @ B[Ntot,512]^T (+bias), A/B given as bf16 hi/lo.
// D = Ah*Bh + Ah*Bl + Al*Bh (fp32 accum). Block 128x128, BK=32, 8 warps.
// SMEM tile rows padded to 40 bf16 (80B) -> conflict-free ldmatrix.
#define TILE_B   10240              // 128 rows * 80 bytes
#define STAGE_B  (4 * TILE_B)       // Ah, Al, Bh, Bl
#define GSMEM_BYTES (2 * STAGE_B)   // double buffer: 81920 B

template <bool BIAS>
__global__ __launch_bounds__(256)
void gemm_mma_x3(const __nv_bfloat16* __restrict__ Ah, const __nv_bfloat16* __restrict__ Al,
                 const __nv_bfloat16* __restrict__ Bh, const __nv_bfloat16* __restrict__ Bl,
                 const float* __restrict__ bias, float* __restrict__ C, int Ntot) {
    extern __shared__ __align__(128) char smem[];
    const uint32_t sb = smem_u32(smem);
    const int tid = threadIdx.x;
    const int wid = tid >> 5, lane = tid & 31;
    const int wm = wid & 3;          // 4 warps along M (32 rows each)
    const int wn = wid >> 2;         // 2 warps along N (64 cols each)
    const int bm = blockIdx.y * 128;
    const int bn = blockIdx.x * 128;

    const __nv_bfloat16* srcs[4] = {
        Ah + (size_t)bm * 512, Al + (size_t)bm * 512,
        Bh + (size_t)bn * 512, Bl + (size_t)bn * 512 };

    // per-thread load coords: 2 chunks of 16B per tile per stage
    const int ch0 = tid, ch1 = tid + 256;
    const int r0 = ch0 >> 2, c0 = (ch0 & 3);
    const int r1 = ch1 >> 2, c1 = (ch1 & 3);

#define ISSUE_STAGE(BUF, K0)                                                   \
    {                                                                          \
        _Pragma("unroll")                                                      \
        for (int t4 = 0; t4 < 4; t4++) {                                       \
            uint32_t base = sb + (BUF) * STAGE_B + t4 * TILE_B;                \
            cp_async16(base + r0 * 80 + c0 * 16,                               \
                       srcs[t4] + (size_t)r0 * 512 + (K0) + c0 * 8);           \
            cp_async16(base + r1 * 80 + c1 * 16,                               \
                       srcs[t4] + (size_t)r1 * 512 + (K0) + c1 * 8);           \
        }                                                                      \
        cp_commit();                                                           \
    }

    float c[2][8][4];
#pragma unroll
    for (int i = 0; i < 2; i++)
#pragma unroll
        for (int j = 0; j < 8; j++)
#pragma unroll
            for (int k = 0; k < 4; k++) c[i][j][k] = 0.f;

    ISSUE_STAGE(0, 0)

    // ldmatrix lane addressing (constant per thread)
    const uint32_t a_row = (lane & 15);
    const uint32_t a_half = (lane >> 4) * 16;
    const uint32_t b_row = (lane & 7) + ((lane >> 4) & 1) * 8;
    const uint32_t b_half = ((lane >> 3) & 1) * 16;

#pragma unroll 1
    for (int kb = 0; kb < 16; kb++) {
        if (kb < 15) ISSUE_STAGE((kb + 1) & 1, (kb + 1) * 32);
        if (kb < 15) cp_wait<1>(); else cp_wait<0>();
        __syncthreads();

        const uint32_t sbase = sb + (kb & 1) * STAGE_B;
#pragma unroll
        for (int p = 0; p < 3; p++) {
            const uint32_t aOff = (p == 2) ? TILE_B : 0;               // Al : Ah
            const uint32_t bOff = (p == 1) ? 3 * TILE_B : 2 * TILE_B;  // Bl : Bh
#pragma unroll
            for (int ks = 0; ks < 2; ks++) {
                uint32_t a[2][4];
#pragma unroll
                for (int mt = 0; mt < 2; mt++) {
                    uint32_t addr = sbase + aOff +
                        (wm * 32 + mt * 16 + a_row) * 80 + a_half + ks * 32;
                    ldsm_x4(addr, a[mt][0], a[mt][1], a[mt][2], a[mt][3]);
                }
#pragma unroll
                for (int nt2 = 0; nt2 < 4; nt2++) {
                    uint32_t b0, b1, b2, b3;
                    uint32_t addr = sbase + bOff +
                        (wn * 64 + nt2 * 16 + b_row) * 80 + b_half + ks * 32;
                    ldsm_x4(addr, b0, b1, b2, b3);
                    mma_16816(c[0][nt2 * 2 + 0], a[0], b0, b1);
                    mma_16816(c[1][nt2 * 2 + 0], a[1], b0, b1);
                    mma_16816(c[0][nt2 * 2 + 1], a[0], b2, b3);
                    mma_16816(c[1][nt2 * 2 + 1], a[1], b2, b3);
                }
            }
        }
        __syncthreads();
    }
#undef ISSUE_STAGE

    // epilogue: C frag (m16n8): c0/c1 -> (row, 2c), (row, 2c+1); c2/c3 -> row+8
#pragma unroll
    for (int mt = 0; mt < 2; mt++) {
        int row = bm + wm * 32 + mt * 16 + (lane >> 2);
#pragma unroll
        for (int nt = 0; nt < 8; nt++) {
            int col = bn + wn * 64 + nt * 8 + 2 * (lane & 3);
            float bx = 0.f, by = 0.f;
            if (BIAS) { bx = __ldg(bias + col); by = __ldg(bias + col + 1); }
            float2 v0 = make_float2(c[mt][nt][0] + bx, c[mt][nt][1] + by);
            float2 v1 = make_float2(c[mt][nt][2] + bx, c[mt][nt][3] + by);
            *reinterpret_cast<float2*>(C + (size_t)row * Ntot + col) = v0;
            *reinterpret_cast<float2*>(C + (size_t)(row + 8) * Ntot + col) = v1;
        }
    }
}

// =================== fp32 SIMT tail (unchanged) =============================
__global__ void make_wq(const float* __restrict__ wql, float* __restrict__ wvec) {
    int t = blockIdx.x * blockDim.x + threadIdx.x;
    if (t < BH * DHq) wvec[t] = wql[t & 63];
}
__global__ void make_wk(const float* __restrict__ wkl, const float* __restrict__ gq,
                        float* __restrict__ wvec) {
    int t = blockIdx.x * blockDim.x + threadIdx.x;
    if (t < BH * DHq) wvec[t] = wkl[t & 63] * gq[t];
}

__global__ __launch_bounds__(256)
void logits_kernel(const float* __restrict__ qkv, int off,
                   const float* __restrict__ wvec,
                   const unsigned char* __restrict__ mask,
                   float* __restrict__ logits) {
    int gw = (blockIdx.x * blockDim.x + threadIdx.x) >> 5;
    int lane = threadIdx.x & 31;
    int np = gw & (Nq - 1);
    int bh = gw >> 13;
    int b = bh >> 3, h = bh & 7;
    int row = h * 1024 + (np >> 3);
    int j0 = (np & 7) * 64;
    const float* p = qkv + (size_t)(b * Nq + row) * QKV_COLS + off + j0;
    const float* w = wvec + bh * 64;
    float s = p[lane] * w[lane] + p[lane + 32] * w[lane + 32];
#pragma unroll
    for (int o = 16; o > 0; o >>= 1) s += __shfl_xor_sync(0xffffffffu, s, o);
    if (lane == 0) {
        float v = s * SCALEq;
        if (mask[b * Nq + np]) v = -1e30f;
        logits[bh * Nq + np] = v;
    }
}

__global__ __launch_bounds__(256)
void max_kernel(const float* __restrict__ logits, float* __restrict__ gmax) {
    int bh = blockIdx.x;
    const float* lrow = logits + bh * Nq;
    int t = threadIdx.x;
    float m = -1e30f;
    for (int n = t; n < Nq; n += 256) m = fmaxf(m, lrow[n]);
    __shared__ float red[256];
    red[t] = m;
    __syncthreads();
    for (int s = 128; s > 0; s >>= 1) {
        if (t < s) red[t] = fmaxf(red[t], red[t + s]);
        __syncthreads();
    }
    if (t == 0) gmax[bh] = red[0];
}

__global__ __launch_bounds__(256)
void partial_reduce(const float* __restrict__ logits,
                    const float* __restrict__ qkv, int off,
                    const float* __restrict__ gmax,
                    float* __restrict__ part) {
    int c = blockIdx.x;
    int bh = blockIdx.y;
    int b = bh >> 3, h = bh & 7;
    const float* lrow = logits + bh * Nq;
    float M = gmax[bh];

    int t = threadIdx.x;
    int d = t & 63, g = t >> 6;
    int n0 = c * 256;

    float vacc = 0.f, sacc = 0.f;
    for (int np = n0 + g; np < n0 + 256; np += 4) {
        int row = h * 1024 + (np >> 3);
        int j0 = (np & 7) * 64;
        float wgt = __expf(lrow[np] - M);
        sacc += wgt;
        vacc += wgt * qkv[(size_t)(b * Nq + row) * QKV_COLS + off + j0 + d];
    }

    __shared__ float sv[4][64];
    __shared__ float ss[4];
    sv[g][d] = vacc;
    if (d == 0) ss[g] = sacc;
    __syncthreads();
    if (t < 64) {
        float* rec = part + (size_t)(bh * CHUNKS + c) * REC;
        rec[t] = sv[0][t] + sv[1][t] + sv[2][t] + sv[3][t];
        if (t == 0) rec[64] = ss[0] + ss[1] + ss[2] + ss[3];
    }
}

__global__ void finalize_reduce(const float* __restrict__ part,
                                float* __restrict__ gout) {
    int bh = blockIdx.x;
    int d = threadIdx.x;
    const float* base = part + (size_t)bh * CHUNKS * REC;
    float v = 0.f, w = 0.f;
#pragma unroll
    for (int c = 0; c < CHUNKS; c++) {
        v += base[c * REC + d];
        w += base[c * REC + 64];
    }
    gout[bh * 64 + d] = v / w;
}

// r = (v * gk) @ W_r^T + b_r + q  -> bf16 hi/lo for GEMM2
__global__ __launch_bounds__(256)
void compute_r_kernel(const float* __restrict__ qkv,
                      const float* __restrict__ gk,
                      const float* __restrict__ W_r,
                      const float* __restrict__ b_r,
                      __nv_bfloat16* __restrict__ Rh,
                      __nv_bfloat16* __restrict__ Rl) {
    constexpr int ROWS = 8;
    int t = threadIdx.x;
    int e = t & 63;
    int cb1 = t >> 6;
    int row0 = blockIdx.x * ROWS;
    int b = row0 >> 13;
    int h = (row0 & (Nq - 1)) >> 10;

    __shared__ float vg[512];
    __shared__ float gkh[64];

    float w[64];
#pragma unroll
    for (int d0 = 0; d0 < 64; d0 += 4) {
        float4 v4 = *reinterpret_cast<const float4*>(W_r + e * 64 + d0);
        w[d0] = v4.x; w[d0 + 1] = v4.y; w[d0 + 2] = v4.z; w[d0 + 3] = v4.w;
    }
    float br = b_r[e];
    if (t < 64) gkh[t] = gk[(b * 8 + h) * 64 + t];
    __syncthreads();

    for (int r = 0; r < ROWS; r++) {
        int m = row0 + r;
        const float* vrow = qkv + (size_t)m * QKV_COLS + 1024;
        vg[t]       = vrow[t]       * gkh[t & 63];
        vg[t + 256] = vrow[t + 256] * gkh[t & 63];
        __syncthreads();

        float a1 = br, a2 = br;
#pragma unroll
        for (int d = 0; d < 64; d += 4) {
            float4 v1 = *reinterpret_cast<const float4*>(&vg[cb1 * 64 + d]);
            float4 v2 = *reinterpret_cast<const float4*>(&vg[(cb1 + 4) * 64 + d]);
            a1 += v1.x * w[d] + v1.y * w[d + 1] + v1.z * w[d + 2] + v1.w * w[d + 3];
            a2 += v2.x * w[d] + v2.y * w[d + 1] + v2.z * w[d + 2] + v2.w * w[d + 3];
        }
        const float* qrow = qkv + (size_t)m * QKV_COLS;
        float r1 = a1 + qrow[cb1 * 64 + e];
        float r2 = a2 + qrow[(cb1 + 4) * 64 + e];
        size_t i1 = (size_t)m * INNERq + cb1 * 64 + e;
        size_t i2 = (size_t)m * INNERq + (cb1 + 4) * 64 + e;
        __nv_bfloat16 h1 = __float2bfloat16(r1);
        __nv_bfloat16 h2 = __float2bfloat16(r2);
        Rh[i1] = h1; Rl[i1] = __float2bfloat16(r1 - __bfloat162float(h1));
        Rh[i2] = h2; Rl[i2] = __float2bfloat16(r2 - __bfloat162float(h2));
        __syncthreads();
    }
}

// ---------------- launcher --------------------------------------------------
extern "C" void kernel_launch(void* const* d_in, const int* in_sizes, int n_in,
                              void* d_out, int out_size) {
    const float* x     = (const float*)d_in[0];
    const unsigned char* mask = (const unsigned char*)d_in[1];
    const float* W_qkv = (const float*)d_in[2];
    const float* w_q   = (const float*)d_in[3];
    const float* w_k   = (const float*)d_in[4];
    const float* W_r   = (const float*)d_in[5];
    const float* b_r   = (const float*)d_in[6];
    const float* W_out = (const float*)d_in[7];
    const float* b_out = (const float*)d_in[8];
    float* out = (float*)d_out;

    float *qkv, *logits, *gq, *gk, *wvec, *part, *gmax;
    __nv_bfloat16 *xh, *xl, *Rh, *Rl, *Wqh, *Wql, *Woh, *Wol;
    cudaGetSymbolAddress((void**)&qkv,    g_qkv);
    cudaGetSymbolAddress((void**)&logits, g_logits);
    cudaGetSymbolAddress((void**)&gq,     g_gq);
    cudaGetSymbolAddress((void**)&gk,     g_gk);
    cudaGetSymbolAddress((void**)&wvec,   g_wvec);
    cudaGetSymbolAddress((void**)&part,   g_part);
    cudaGetSymbolAddress((void**)&gmax,   g_max);
    cudaGetSymbolAddress((void**)&xh,     g_xh);
    cudaGetSymbolAddress((void**)&xl,     g_xl);
    cudaGetSymbolAddress((void**)&Rh,     g_Rh);
    cudaGetSymbolAddress((void**)&Rl,     g_Rl);
    cudaGetSymbolAddress((void**)&Wqh,    g_Wqh);
    cudaGetSymbolAddress((void**)&Wql,    g_Wql);
    cudaGetSymbolAddress((void**)&Woh,    g_Woh);
    cudaGetSymbolAddress((void**)&Wol,    g_Wol);

    static int smem_set = 0;
    if (!smem_set) {
        cudaFuncSetAttribute(gemm_mma_x3<false>,
                             cudaFuncAttributeMaxDynamicSharedMemorySize, GSMEM_BYTES);
        cudaFuncSetAttribute(gemm_mma_x3<true>,
                             cudaFuncAttributeMaxDynamicSharedMemorySize, GSMEM_BYTES);
        smem_set = 1;
    }

    // 0) hi/lo splits of x and the weight matrices
    split_kernel<<<(M_TOTAL * DIMq) / 1024, 256>>>(x, xh, xl);
    split_kernel<<<(QKV_COLS * DIMq) / 1024, 256>>>(W_qkv, Wqh, Wql);
    split_kernel<<<(DIMq * INNERq) / 1024, 256>>>(W_out, Woh, Wol);

    // 1) qkv = x @ W_qkv^T  (HMMA bf16 x3)
    gemm_mma_x3<false><<<dim3(QKV_COLS / 128, M_TOTAL / 128), 256, GSMEM_BYTES>>>(
        xh, xl, Wqh, Wql, nullptr, qkv, QKV_COLS);

    // 2) q softmax -> global_q
    make_wq<<<(BH * DHq + 255) / 256, 256>>>(w_q, wvec);
    logits_kernel<<<BH * Nq / 8, 256>>>(qkv, 0, wvec, mask, logits);
    max_kernel<<<BH, 256>>>(logits, gmax);
    partial_reduce<<<dim3(CHUNKS, BH), 256>>>(logits, qkv, 0, gmax, part);
    finalize_reduce<<<BH, 64>>>(part, gq);

    // 3) k softmax -> global_k
    make_wk<<<(BH * DHq + 255) / 256, 256>>>(w_k, gq, wvec);
    logits_kernel<<<BH * Nq / 8, 256>>>(qkv, DIMq, wvec, mask, logits);
    max_kernel<<<BH, 256>>>(logits, gmax);
    partial_reduce<<<dim3(CHUNKS, BH), 256>>>(logits, qkv, DIMq, gmax, part);
    finalize_reduce<<<BH, 64>>>(part, gk);

    // 4) r = (v*gk) @ W_r^T + b_r + q  (writes bf16 hi/lo)
    compute_r_kernel<<<M_TOTAL / 8, 256>>>(qkv, gk, W_r, b_r, Rh, Rl);

    // 5) out = r @ W_out^T + b_out  (HMMA bf16 x3)
    gemm_mma_x3<true><<<dim3(INNERq / 128, M_TOTAL / 128), 256, GSMEM_BYTES>>>(
        Rh, Rl, Woh, Wol, b_out, out, INNERq);
}